// round 1
// baseline (speedup 1.0000x reference)
#include <cuda_runtime.h>

// Demolition_Conv2d: grouped conv (Cin groups of 1->Cout 3x3, pad 1) + bias,
// per-Cin-partial quant-dequant (5-bit, scale=15/9), sum over Cin.
// out[b,co,h,w] = sum_ci round(SCALE*(b[ci,co] + conv3x3(x[b,ci], W[ci,co])))/SCALE
//
// Strategy: fp32-pipe-bound problem -> use Blackwell packed f32x2 math
// (fma.rn.f32x2 / add.rn.f32x2). Each thread computes a horizontal pixel
// PAIR for all 32 couts; rounding via magic-constant RNE trick (2 packed adds).

#define CIN  16
#define COUT 32
#define HH   112
#define WW   112

typedef unsigned long long f2;  // carrier for packed f32x2

__device__ __forceinline__ f2 pk2(float lo, float hi) {
    f2 r; asm("mov.b64 %0, {%1, %2};" : "=l"(r) : "f"(lo), "f"(hi)); return r;
}
__device__ __forceinline__ f2 fma2(f2 a, f2 b, f2 c) {
    f2 d; asm("fma.rn.f32x2 %0, %1, %2, %3;" : "=l"(d) : "l"(a), "l"(b), "l"(c)); return d;
}
__device__ __forceinline__ f2 add2(f2 a, f2 b) {
    f2 d; asm("add.rn.f32x2 %0, %1, %2;" : "=l"(d) : "l"(a), "l"(b)); return d;
}
__device__ __forceinline__ f2 mul2(f2 a, f2 b) {
    f2 d; asm("mul.rn.f32x2 %0, %1, %2;" : "=l"(d) : "l"(a), "l"(b)); return d;
}

__global__ __launch_bounds__(128, 4)
void demolition_conv2d_kernel(const float* __restrict__ x,
                              const float* __restrict__ Wt,
                              const float* __restrict__ bias,
                              float* __restrict__ out)
{
    // Weights & bias duplicated into packed pairs, broadcast-read from shared.
    __shared__ f2 sW[CIN * COUT * 9];   // [cin][cout][k]
    __shared__ f2 sB[CIN * COUT];       // [cin][cout]

    for (int i = threadIdx.x; i < CIN * COUT * 9; i += blockDim.x) {
        float v = Wt[i];
        sW[i] = pk2(v, v);
    }
    for (int i = threadIdx.x; i < CIN * COUT; i += blockDim.x) {
        float v = bias[i];
        sB[i] = pk2(v, v);
    }
    __syncthreads();

    // 8 * 112 * 56 = 50176 pixel-pairs; grid exactly covers it.
    int pair = blockIdx.x * blockDim.x + threadIdx.x;
    int pw = pair % 56;            // pair column index
    int t1 = pair / 56;
    int h  = t1 % HH;
    int b  = t1 / HH;
    int w0 = pw * 2;               // left pixel of the pair (even -> 8B aligned stores)

    const bool up = (h > 0);
    const bool dn = (h < HH - 1);
    const bool lf = (w0 > 0);
    const bool rt = (w0 < WW - 2);

    const float SCALEf = 15.0f / 9.0f;
    const float INVf   = 1.0f / (15.0f / 9.0f);
    const float MAGICf = 12582912.0f;           // 1.5 * 2^23 -> RNE round trick
    const f2 SCALE2 = pk2(SCALEf,  SCALEf);
    const f2 INV2   = pk2(INVf,    INVf);
    const f2 MAG2   = pk2(MAGICf,  MAGICf);
    const f2 NMAG2  = pk2(-MAGICf, -MAGICf);

    f2 acc[COUT];
#pragma unroll
    for (int c = 0; c < COUT; ++c) acc[c] = 0ULL;

#pragma unroll 1
    for (int cin = 0; cin < CIN; ++cin) {
        const float* base = x + (((b * CIN + cin) * HH + h) * WW) + w0;

        // Load 3x4 input patch (zero-padded), build 9 shifted pairs.
        f2 p[9];
#pragma unroll
        for (int r = 0; r < 3; ++r) {
            const float* rp = base + (r - 1) * WW;
            bool rowok = (r == 0) ? up : ((r == 2) ? dn : true);
            float a0 = (rowok && lf) ? rp[-1] : 0.0f;
            float a1 = rowok ? rp[0] : 0.0f;
            float a2 = rowok ? rp[1] : 0.0f;
            float a3 = (rowok && rt) ? rp[2] : 0.0f;
            p[r * 3 + 0] = pk2(a0, a1);
            p[r * 3 + 1] = pk2(a1, a2);
            p[r * 3 + 2] = pk2(a2, a3);
        }

        const f2* wc = &sW[cin * COUT * 9];
        const f2* bc = &sB[cin * COUT];

#pragma unroll
        for (int c = 0; c < COUT; ++c) {
            f2 y = bc[c];
#pragma unroll
            for (int k = 0; k < 9; ++k)
                y = fma2(p[k], wc[c * 9 + k], y);
            // t = y * scale; q = rne(t); acc += q * (1/scale)
            f2 t = mul2(y, SCALE2);
            f2 m = add2(t, MAG2);
            f2 q = add2(m, NMAG2);
            acc[c] = fma2(q, INV2, acc[c]);
        }
    }

    // Store: pair is contiguous in W, 8-byte aligned (w0 even, row stride even).
    float* ob = out + ((b * COUT) * HH + h) * WW + w0;
#pragma unroll
    for (int c = 0; c < COUT; ++c) {
        *reinterpret_cast<f2*>(ob + c * HH * WW) = acc[c];
    }
}

extern "C" void kernel_launch(void* const* d_in, const int* in_sizes, int n_in,
                              void* d_out, int out_size)
{
    const float* x    = (const float*)d_in[0];   // [8,16,112,112]
    const float* Wt   = (const float*)d_in[1];   // [16,32,1,3,3]
    const float* bias = (const float*)d_in[2];   // [16,32]
    float* out        = (float*)d_out;           // [8,32,112,112]

    // 50176 pixel-pairs / 128 threads = 392 blocks, exact cover.
    demolition_conv2d_kernel<<<392, 128>>>(x, Wt, bias, out);
}

// round 2
// speedup vs baseline: 1.0599x; 1.0599x over previous
#include <cuda_runtime.h>

// Demolition_Conv2d: grouped conv (16 groups of 1->32, 3x3, pad 1) + bias,
// per-(cin,cout) 5-bit quant-dequant (scale=15/9), sum over cin.
//
// R2: LDS-bound fix. Each thread computes 4 consecutive pixels (2 f32x2 pairs)
// for 16 couts. Weights pre-scaled by SCALE and packed as f32x2 pairs in smem,
// 10 f2 per (cin,cout) -> 5 x LDS.128. Quantized partials accumulated as
// integers (add2), one mul by 1/SCALE at the end. RNE via magic-constant adds.

#define CIN  16
#define COUT 32
#define HH   112
#define WW   112

typedef unsigned long long f2;

__device__ __forceinline__ f2 pk2(float lo, float hi) {
    f2 r; asm("mov.b64 %0, {%1, %2};" : "=l"(r) : "f"(lo), "f"(hi)); return r;
}
__device__ __forceinline__ f2 fma2(f2 a, f2 b, f2 c) {
    f2 d; asm("fma.rn.f32x2 %0, %1, %2, %3;" : "=l"(d) : "l"(a), "l"(b), "l"(c)); return d;
}
__device__ __forceinline__ f2 add2(f2 a, f2 b) {
    f2 d; asm("add.rn.f32x2 %0, %1, %2;" : "=l"(d) : "l"(a), "l"(b)); return d;
}
__device__ __forceinline__ f2 mul2(f2 a, f2 b) {
    f2 d; asm("mul.rn.f32x2 %0, %1, %2;" : "=l"(d) : "l"(a), "l"(b)); return d;
}

__global__ __launch_bounds__(128, 4)
void demolition_conv2d_kernel(const float* __restrict__ x,
                              const float* __restrict__ Wt,
                              const float* __restrict__ bias,
                              float* __restrict__ out)
{
    // Per-block weights: this block's 16 couts only.
    // Entry layout per (cin, lc): [w0..w8, bias] * SCALE, duplicated pairs.
    __shared__ __align__(16) f2 sW[CIN * 16 * 10];   // 20 KB

    const float SCALEf = 15.0f / 9.0f;
    const float INVf   = 9.0f / 15.0f;
    const float MAGICf = 12582912.0f;   // 1.5 * 2^23

    // Thread mapping: g in [0, 50176). Half 0: blocks 0..195, half 1: 196..391.
    int g = blockIdx.x * 128 + threadIdx.x;
    int co_half = g / 25088;            // uniform per block (25088 = 196*128)
    int q  = g % 25088;                 // pixel-quad index
    int qw = q % 28;                    // 112/4 quads per row
    int t1 = q / 28;
    int h  = t1 % HH;
    int b  = t1 / HH;
    int w0 = qw * 4;
    int co_base = co_half * 16;

    // Fill shared weights (scaled, duplicated).
    for (int i = threadIdx.x; i < CIN * 16 * 10; i += 128) {
        int e   = i / 10;
        int k   = i % 10;
        int cin = e / 16;
        int lc  = e % 16;
        int co  = co_base + lc;
        float v = (k < 9) ? Wt[(cin * COUT + co) * 9 + k] : bias[cin * COUT + co];
        v *= SCALEf;
        sW[i] = pk2(v, v);
    }
    __syncthreads();

    const bool up = (h > 0);
    const bool dn = (h < HH - 1);
    const bool lf = (w0 > 0);
    const bool rt = (w0 < WW - 4);

    const f2 MAG2  = pk2(MAGICf,  MAGICf);
    const f2 NMAG2 = pk2(-MAGICf, -MAGICf);
    const f2 INV2  = pk2(INVf,    INVf);

    f2 acc0[16], acc1[16];
#pragma unroll
    for (int c = 0; c < 16; ++c) { acc0[c] = 0ULL; acc1[c] = 0ULL; }

#pragma unroll 1
    for (int cin = 0; cin < CIN; ++cin) {
        const float* base = x + (((b * CIN + cin) * HH + h) * WW) + w0;

        // Load 3 rows x 6 floats (zero-padded), build 5 shifted pairs per row.
        f2 p[3][5];
#pragma unroll
        for (int r = 0; r < 3; ++r) {
            const float* rp = base + (r - 1) * WW;
            bool rowok = (r == 0) ? up : ((r == 2) ? dn : true);
            float am1 = (rowok && lf) ? rp[-1] : 0.0f;
            float4 v  = rowok ? *reinterpret_cast<const float4*>(rp)
                              : make_float4(0.f, 0.f, 0.f, 0.f);
            float a4  = (rowok && rt) ? rp[4] : 0.0f;
            p[r][0] = pk2(am1, v.x);
            p[r][1] = pk2(v.x, v.y);
            p[r][2] = pk2(v.y, v.z);
            p[r][3] = pk2(v.z, v.w);
            p[r][4] = pk2(v.w, a4);
        }

        const ulonglong2* wbase =
            reinterpret_cast<const ulonglong2*>(&sW[cin * 16 * 10]);

#pragma unroll
        for (int c = 0; c < 16; ++c) {
            ulonglong2 w01 = wbase[c * 5 + 0];
            ulonglong2 w23 = wbase[c * 5 + 1];
            ulonglong2 w45 = wbase[c * 5 + 2];
            ulonglong2 w67 = wbase[c * 5 + 3];
            ulonglong2 w8b = wbase[c * 5 + 4];   // .x = w8, .y = bias

            f2 y0 = w8b.y;
            f2 y1 = w8b.y;
            // row 0
            y0 = fma2(p[0][0], w01.x, y0);  y1 = fma2(p[0][2], w01.x, y1);
            y0 = fma2(p[0][1], w01.y, y0);  y1 = fma2(p[0][3], w01.y, y1);
            y0 = fma2(p[0][2], w23.x, y0);  y1 = fma2(p[0][4], w23.x, y1);
            // row 1
            y0 = fma2(p[1][0], w23.y, y0);  y1 = fma2(p[1][2], w23.y, y1);
            y0 = fma2(p[1][1], w45.x, y0);  y1 = fma2(p[1][3], w45.x, y1);
            y0 = fma2(p[1][2], w45.y, y0);  y1 = fma2(p[1][4], w45.y, y1);
            // row 2
            y0 = fma2(p[2][0], w67.x, y0);  y1 = fma2(p[2][2], w67.x, y1);
            y0 = fma2(p[2][1], w67.y, y0);  y1 = fma2(p[2][3], w67.y, y1);
            y0 = fma2(p[2][2], w8b.x, y0);  y1 = fma2(p[2][4], w8b.x, y1);

            // RNE round to integer (|y| << 2^22), accumulate q exactly.
            f2 q0 = add2(add2(y0, MAG2), NMAG2);
            f2 q1 = add2(add2(y1, MAG2), NMAG2);
            acc0[c] = add2(acc0[c], q0);
            acc1[c] = add2(acc1[c], q1);
        }
    }

    // Store: 4 consecutive pixels per cout -> one 16B store each.
    float* ob = out + ((b * COUT + co_base) * HH + h) * WW + w0;
#pragma unroll
    for (int c = 0; c < 16; ++c) {
        ulonglong2 v;
        v.x = mul2(acc0[c], INV2);
        v.y = mul2(acc1[c], INV2);
        *reinterpret_cast<ulonglong2*>(ob + c * HH * WW) = v;
    }
}

extern "C" void kernel_launch(void* const* d_in, const int* in_sizes, int n_in,
                              void* d_out, int out_size)
{
    const float* x    = (const float*)d_in[0];   // [8,16,112,112]
    const float* Wt   = (const float*)d_in[1];   // [16,32,1,3,3]
    const float* bias = (const float*)d_in[2];   // [16,32]
    float* out        = (float*)d_out;           // [8,32,112,112]

    demolition_conv2d_kernel<<<392, 128>>>(x, Wt, bias, out);
}